// round 12
// baseline (speedup 1.0000x reference)
#include <cuda_runtime.h>
#include <cuda_bf16.h>
#include <cstdint>

// ---------------------------------------------------------------------------
// AggrEGATConv fused EGAT convolution.
//   output: res_n [N,16] followed by res_e [E,16], f32
// ---------------------------------------------------------------------------

#define MAXN 100000
#define MAXE 1600000

__device__ float g_fni [(size_t)MAXN * 64];
__device__ float g_fnj [(size_t)MAXN * 64];
__device__ float g_hsrc[(size_t)MAXN * 64];
__device__ float g_ex  [(size_t)MAXE * 4];
__device__ float g_z   [(size_t)MAXN * 4];
// W_fij bf16 hi/lo, transposed (wt[n][kp]), packed (k,k+1) u32
__device__ unsigned g_wth[64 * 32];
__device__ unsigned g_wtl[64 * 32];

// ---- helpers ---------------------------------------------------------------
__device__ __forceinline__ unsigned long long pack2(float x, float y) {
    unsigned long long r;
    asm("mov.b64 %0, {%1, %2};"
        : "=l"(r) : "r"(__float_as_uint(x)), "r"(__float_as_uint(y)));
    return r;
}
__device__ __forceinline__ unsigned long long ffma2(unsigned long long a,
                                                    unsigned long long b,
                                                    unsigned long long c) {
    unsigned long long d;
    asm("fma.rn.f32x2 %0, %1, %2, %3;" : "=l"(d) : "l"(a), "l"(b), "l"(c));
    return d;
}
__device__ __forceinline__ void red_add_v4(float* p, float a, float b,
                                           float c, float d) {
    asm volatile("red.global.add.v4.f32 [%0], {%1, %2, %3, %4};"
                 :: "l"(p), "f"(a), "f"(b), "f"(c), "f"(d) : "memory");
}
// split (v0, v1) into packed bf16x2 hi word + packed bf16x2 residual word.
__device__ __forceinline__ void bf16split2(float v0, float v1,
                                           unsigned& h, unsigned& l) {
    asm("cvt.rn.bf16x2.f32 %0, %1, %2;" : "=r"(h) : "f"(v1), "f"(v0));
    float f0 = __uint_as_float(h << 16);
    float f1 = __uint_as_float(h & 0xffff0000u);
    float r0 = v0 - f0;
    float r1 = v1 - f1;
    asm("cvt.rn.bf16x2.f32 %0, %1, %2;" : "=r"(l) : "f"(r1), "f"(r0));
}
__device__ __forceinline__ void mma16816(float& d0, float& d1, float& d2,
                                         float& d3, unsigned a0, unsigned a1,
                                         unsigned a2, unsigned a3,
                                         unsigned b0, unsigned b1) {
    asm volatile(
        "mma.sync.aligned.m16n8k16.row.col.f32.bf16.bf16.f32 "
        "{%0,%1,%2,%3}, {%4,%5,%6,%7}, {%8,%9}, {%0,%1,%2,%3};"
        : "+f"(d0), "+f"(d1), "+f"(d2), "+f"(d3)
        : "r"(a0), "r"(a1), "r"(a2), "r"(a3), "r"(b0), "r"(b1));
}

// edge_main strides (words): 36 mod 32 == 4 -> conflict-free; even -> aligned
#define XS     36
#define WS     36
#define WREG   1152
#define EPS    68

// ---------------------------------------------------------------------------
// Kernel 1 ("phase1"): node GEMMs (FFMA2) + zero(out_n, z) + wsplit.
//   grid = (ceil(N/256), 3).  All outputs consumed only by later kernels.
// ---------------------------------------------------------------------------
__global__ __launch_bounds__(256)
void phase1(const float* __restrict__ nf,
            const float* __restrict__ Wni,
            const float* __restrict__ Wnj,
            const float* __restrict__ Wsrc,
            const float* __restrict__ bsrc,
            const float* __restrict__ Wfij,
            float* __restrict__ out_n,
            int N)
{
    __shared__ ulonglong2 sW[128 * 16];
    __shared__ float      sb[64];

    const int tid = threadIdx.x;
    const int bid = blockIdx.y * gridDim.x + blockIdx.x;
    const int nthr = gridDim.x * 3 * 256;

    // ---- merged housekeeping (grid-strided) ----
    for (long long i = (long long)bid * 256 + tid; i < (long long)N * 16;
         i += nthr)
        out_n[i] = 0.0f;
    for (long long i = (long long)bid * 256 + tid; i < (long long)N * 4;
         i += nthr)
        g_z[i] = 0.0f;
    if (bid == 0) {
        for (int j = tid; j < 2048; j += 256) {
            int n = j >> 5, kp = j & 31;
            float w0 = Wfij[(2 * kp) * 64 + n];
            float w1 = Wfij[(2 * kp + 1) * 64 + n];
            unsigned h, l;
            bf16split2(w0, w1, h, l);
            g_wth[j] = h;
            g_wtl[j] = l;
        }
    }

    // ---- node GEMM (unchanged R7 core) ----
    const int which = blockIdx.y;
    const float* W = (which == 0) ? Wni : (which == 1) ? Wnj : Wsrc;
    float* out = (which == 0) ? g_fni : (which == 1) ? g_fnj : g_hsrc;

    const float4* Wv = (const float4*)W;
    for (int i = tid; i < 2048; i += 256) {
        float4 w = Wv[i];
        ulonglong2 u;
        u.x = pack2(w.x, w.y);
        u.y = pack2(w.z, w.w);
        sW[i] = u;
    }
    if (tid < 64)
        sb[tid] = (which == 2) ? bsrc[tid] : 0.0f;
    __syncthreads();

    const int n = blockIdx.x * 256 + tid;
    if (n >= N) return;

    unsigned long long acc[32];
#pragma unroll
    for (int p = 0; p < 32; ++p) acc[p] = 0ull;

    const float4* xv = (const float4*)(nf + (size_t)n * 128);
#pragma unroll 4
    for (int k4 = 0; k4 < 32; ++k4) {
        float4 xq = xv[k4];
#pragma unroll
        for (int j = 0; j < 4; ++j) {
            float xs = (j == 0) ? xq.x : (j == 1) ? xq.y : (j == 2) ? xq.z : xq.w;
            unsigned long long xx = pack2(xs, xs);
            const int k = k4 * 4 + j;
#pragma unroll
            for (int q = 0; q < 16; ++q) {
                ulonglong2 w = sW[k * 16 + q];
                acc[2 * q]     = ffma2(xx, w.x, acc[2 * q]);
                acc[2 * q + 1] = ffma2(xx, w.y, acc[2 * q + 1]);
            }
        }
    }

    float* o = out + (size_t)n * 64;
#pragma unroll
    for (int p = 0; p < 32; ++p) {
        float2 v = *(float2*)&acc[p];
        o[2 * p]     = v.x + sb[2 * p];
        o[2 * p + 1] = v.y + sb[2 * p + 1];
    }
}

// ---------------------------------------------------------------------------
// Kernel 2: edge pass 1 via tensor cores (bf16x3, R10/R11 structure).
// ---------------------------------------------------------------------------
__global__ __launch_bounds__(256, 4)
void edge_main(const float* __restrict__ efeats,
               const int*   __restrict__ src,
               const int*   __restrict__ dst,
               const float* __restrict__ attn,
               const float* __restrict__ bias_e,
               float* __restrict__ out_e,
               int E)
{
    extern __shared__ char dyns[];
    unsigned* s_wh = (unsigned*)dyns;
    unsigned* s_wl = s_wh + 64 * WS;
    unsigned* s_x  = s_wl + 64 * WS;
    float*    s_attn = (float*)(s_x + 8 * WREG);
    float*    s_bias = s_attn + 64;

    const int tid  = threadIdx.x;
    const int lane = tid & 31;
    const int w    = tid >> 5;

    for (int j = tid; j < 2048; j += 256) {
        int n = j >> 5, kp = j & 31;
        s_wh[n * WS + kp] = g_wth[j];
        s_wl[n * WS + kp] = g_wtl[j];
    }
    if (tid < 64) {
        s_attn[tid] = attn[tid];
        s_bias[tid] = bias_e[tid];
    }

    const long long eblk = (long long)blockIdx.x * 128;
    {
        const float4* ef4 = (const float4*)efeats;
#pragma unroll
        for (int i = 0; i < 8; ++i) {
            int idx = i * 256 + tid;
            int e  = idx >> 4;
            int ch = idx & 15;
            float4 v = make_float4(0.f, 0.f, 0.f, 0.f);
            if (eblk + e < E) v = ef4[(eblk + e) * 16 + ch];
            unsigned h0, l0, h1, l1;
            bf16split2(v.x, v.y, h0, l0);
            bf16split2(v.z, v.w, h1, l1);
            unsigned* base = s_x + (e >> 4) * WREG + (e & 15) * XS + ch * 2;
            *(uint2*)(base)            = make_uint2(h0, h1);
            *(uint2*)(base + 16 * XS)  = make_uint2(l0, l1);
        }
    }
    __syncthreads();

    const long long ewarp = eblk + w * 16;
    const int g = lane >> 2;
    const int q = lane & 3;

    int myS = 0, myD = 0;
    if (lane < 16 && ewarp + lane < E) {
        myS = src[ewarp + lane];
        myD = dst[ewarp + lane];
    }

    float acc[8][4];
#pragma unroll
    for (int nt = 0; nt < 8; ++nt)
#pragma unroll
        for (int i = 0; i < 4; ++i) acc[nt][i] = 0.0f;

    const unsigned* xh0 = s_x + w * WREG + g * XS;
    const unsigned* xh8 = xh0 + 8 * XS;
    const unsigned* xl0 = xh0 + 16 * XS;
    const unsigned* xl8 = xl0 + 8 * XS;

#pragma unroll
    for (int kt = 0; kt < 4; ++kt) {
        const int kp = kt * 8 + q;
        unsigned ah0 = xh0[kp],     ah1 = xh8[kp];
        unsigned ah2 = xh0[kp + 4], ah3 = xh8[kp + 4];
        unsigned al0 = xl0[kp],     al1 = xl8[kp];
        unsigned al2 = xl0[kp + 4], al3 = xl8[kp + 4];
#pragma unroll
        for (int nt = 0; nt < 8; ++nt) {
            const unsigned* wb  = s_wh + (nt * 8 + g) * WS + kp;
            const unsigned* wlb = s_wl + (nt * 8 + g) * WS + kp;
            unsigned bh0 = wb[0],  bh1 = wb[4];
            unsigned bl0 = wlb[0], bl1 = wlb[4];
            mma16816(acc[nt][0], acc[nt][1], acc[nt][2], acc[nt][3],
                     ah0, ah1, ah2, ah3, bh0, bh1);
            mma16816(acc[nt][0], acc[nt][1], acc[nt][2], acc[nt][3],
                     ah0, ah1, ah2, ah3, bl0, bl1);
            mma16816(acc[nt][0], acc[nt][1], acc[nt][2], acc[nt][3],
                     al0, al1, al2, al3, bh0, bh1);
        }
    }
    __syncwarp();

    float* epiw = (float*)(s_x + w * WREG);
#pragma unroll
    for (int nt = 0; nt < 8; ++nt) {
        const int c = nt * 8 + 2 * q;
        *(float2*)(epiw + g * EPS + c)       = make_float2(acc[nt][0], acc[nt][1]);
        *(float2*)(epiw + (g + 8) * EPS + c) = make_float2(acc[nt][2], acc[nt][3]);
    }
    __syncwarp();

    const int half = lane >> 4;
    const int hl   = lane & 15;
    const float4 bias4 = *(const float4*)(s_bias + 4 * hl);
    const float4 attn4 = *(const float4*)(s_attn + 4 * hl);

#pragma unroll 2
    for (int r2 = 0; r2 < 8; ++r2) {
        const int row = 2 * r2 + half;
        const long long e_r = ewarp + row;
        if (ewarp + 2 * r2 >= E) break;
        const bool valid = (e_r < E);
        const int s_r = __shfl_sync(0xffffffffu, myS, row);
        const int d_r = __shfl_sync(0xffffffffu, myD, row);

        float4 fa = *(const float4*)(g_fni + (size_t)s_r * 64 + 4 * hl);
        float4 fb = *(const float4*)(g_fnj + (size_t)d_r * 64 + 4 * hl);
        float4 ac = *(const float4*)(epiw + row * EPS + 4 * hl);

        float y0 = ac.x + fa.x + fb.x + bias4.x;
        float y1 = ac.y + fa.y + fb.y + bias4.y;
        float y2 = ac.z + fa.z + fb.z + bias4.z;
        float y3 = ac.w + fa.w + fb.w + bias4.w;
        y0 = (y0 > 0.0f) ? y0 : 0.01f * y0;
        y1 = (y1 > 0.0f) ? y1 : 0.01f * y1;
        y2 = (y2 > 0.0f) ? y2 : 0.01f * y2;
        y3 = (y3 > 0.0f) ? y3 : 0.01f * y3;

        float lp = y0 * attn4.x + y1 * attn4.y + y2 * attn4.z + y3 * attn4.w;
        lp += __shfl_xor_sync(0xffffffffu, lp, 1);
        lp += __shfl_xor_sync(0xffffffffu, lp, 2);

        y0 += __shfl_xor_sync(0xffffffffu, y0, 4);
        y0 += __shfl_xor_sync(0xffffffffu, y0, 8);
        y1 += __shfl_xor_sync(0xffffffffu, y1, 4);
        y1 += __shfl_xor_sync(0xffffffffu, y1, 8);
        y2 += __shfl_xor_sync(0xffffffffu, y2, 4);
        y2 += __shfl_xor_sync(0xffffffffu, y2, 8);
        y3 += __shfl_xor_sync(0xffffffffu, y3, 4);
        y3 += __shfl_xor_sync(0xffffffffu, y3, 8);

        if (valid && hl < 4)
            *(float4*)(out_e + (size_t)e_r * 16 + 4 * hl) =
                make_float4(0.25f * y0, 0.25f * y1, 0.25f * y2, 0.25f * y3);

        const int hb = lane & 16;
        float l0 = __shfl_sync(0xffffffffu, lp, hb + 0);
        float l1 = __shfl_sync(0xffffffffu, lp, hb + 4);
        float l2 = __shfl_sync(0xffffffffu, lp, hb + 8);
        float l3 = __shfl_sync(0xffffffffu, lp, hb + 12);
        if (valid && hl == 0) {
            float e0 = expf(l0), e1 = expf(l1), e2 = expf(l2), e3 = expf(l3);
            *(float4*)(g_ex + (size_t)e_r * 4) = make_float4(e0, e1, e2, e3);
            red_add_v4(&g_z[(size_t)d_r * 4], e0, e1, e2, e3);
        }
    }
}

// ---------------------------------------------------------------------------
// Kernel 3: invert z once per (node, head)
// ---------------------------------------------------------------------------
__global__ void inv_z(int N) {
    int i = blockIdx.x * 256 + threadIdx.x;
    if (i < N * 4) g_z[i] = __frcp_rn(g_z[i]);
}

// ---------------------------------------------------------------------------
// Kernel 4: edge pass 2.  4 lanes/edge, 2 edges per lane-group (MLP x2).
// ---------------------------------------------------------------------------
__global__ __launch_bounds__(256)
void edge_aggr(const int* __restrict__ src,
               const int* __restrict__ dst,
               float* __restrict__ out_n,
               int E)
{
    const int tid  = threadIdx.x;
    const int lane = tid & 31;
    const int t    = lane & 3;
    const long long ebase = (long long)blockIdx.x * 128 + (tid >> 5) * 16
                            + (lane >> 2);
    const long long e0 = ebase;
    const long long e1 = ebase + 8;
    const bool v0ok = (e0 < E);
    const bool v1ok = (e1 < E);
    if (!v0ok) return;

    const int s0 = src[e0];
    const int d0 = dst[e0];
    const int s1 = v1ok ? src[e1] : 0;
    const int d1 = v1ok ? dst[e1] : 0;

    float4 exA = *(const float4*)(g_ex + (size_t)e0 * 4);
    float4 ziA = *(const float4*)(g_z  + (size_t)d0 * 4);
    float4 exB = make_float4(0.f, 0.f, 0.f, 0.f);
    float4 ziB = make_float4(0.f, 0.f, 0.f, 0.f);
    if (v1ok) {
        exB = *(const float4*)(g_ex + (size_t)e1 * 4);
        ziB = *(const float4*)(g_z  + (size_t)d1 * 4);
    }

    const float* hrA = g_hsrc + (size_t)s0 * 64 + 4 * t;
    const float* hrB = g_hsrc + (size_t)s1 * 64 + 4 * t;
    float4 a0v = *(const float4*)(hrA);
    float4 a1v = *(const float4*)(hrA + 16);
    float4 a2v = *(const float4*)(hrA + 32);
    float4 a3v = *(const float4*)(hrA + 48);
    float4 b0v, b1v, b2v, b3v;
    if (v1ok) {
        b0v = *(const float4*)(hrB);
        b1v = *(const float4*)(hrB + 16);
        b2v = *(const float4*)(hrB + 32);
        b3v = *(const float4*)(hrB + 48);
    }

    {
        const float a0 = 0.25f * exA.x * ziA.x;
        const float a1 = 0.25f * exA.y * ziA.y;
        const float a2 = 0.25f * exA.z * ziA.z;
        const float a3 = 0.25f * exA.w * ziA.w;
        float m0 = a0 * a0v.x + a1 * a1v.x + a2 * a2v.x + a3 * a3v.x;
        float m1 = a0 * a0v.y + a1 * a1v.y + a2 * a2v.y + a3 * a3v.y;
        float m2 = a0 * a0v.z + a1 * a1v.z + a2 * a2v.z + a3 * a3v.z;
        float m3 = a0 * a0v.w + a1 * a1v.w + a2 * a2v.w + a3 * a3v.w;
        red_add_v4(out_n + (size_t)d0 * 16 + 4 * t, m0, m1, m2, m3);
    }
    if (v1ok) {
        const float a0 = 0.25f * exB.x * ziB.x;
        const float a1 = 0.25f * exB.y * ziB.y;
        const float a2 = 0.25f * exB.z * ziB.z;
        const float a3 = 0.25f * exB.w * ziB.w;
        float m0 = a0 * b0v.x + a1 * b1v.x + a2 * b2v.x + a3 * b3v.x;
        float m1 = a0 * b0v.y + a1 * b1v.y + a2 * b2v.y + a3 * b3v.y;
        float m2 = a0 * b0v.z + a1 * b1v.z + a2 * b2v.z + a3 * b3v.z;
        float m3 = a0 * b0v.w + a1 * b1v.w + a2 * b2v.w + a3 * b3v.w;
        red_add_v4(out_n + (size_t)d1 * 16 + 4 * t, m0, m1, m2, m3);
    }
}

// ---------------------------------------------------------------------------
extern "C" void kernel_launch(void* const* d_in, const int* in_sizes, int n_in,
                              void* d_out, int out_size)
{
    const float* nfeats = (const float*)d_in[0];
    const float* efeats = (const float*)d_in[1];
    const int*   src    = (const int*)  d_in[2];
    const int*   dst    = (const int*)  d_in[3];
    const float* Wni    = (const float*)d_in[4];
    const float* Wnj    = (const float*)d_in[5];
    const float* Wfij   = (const float*)d_in[6];
    const float* Wsrc   = (const float*)d_in[7];
    const float* bsrc   = (const float*)d_in[8];
    const float* attn   = (const float*)d_in[9];
    const float* biase  = (const float*)d_in[10];

    const int N = in_sizes[0] / 128;
    const int E = in_sizes[2];

    float* out_n = (float*)d_out;
    float* out_e = out_n + (size_t)N * 16;

    static int smem_set = 0;
    const int EM_SMEM = (64 * WS * 2 + 8 * WREG + 128) * 4;  // 55808 B
    if (!smem_set) {
        cudaFuncSetAttribute(edge_main,
                             cudaFuncAttributeMaxDynamicSharedMemorySize,
                             EM_SMEM);
        smem_set = 1;
    }

    // launch order: idx 3 (ncu's pick) = edge_aggr this round
    dim3 g1((N + 255) / 256, 3);
    phase1<<<g1, 256>>>(nfeats, Wni, Wnj, Wsrc, bsrc, Wfij, out_n, N);

    edge_main<<<(E + 127) / 128, 256, EM_SMEM>>>(efeats, src, dst,
                                                 attn, biase, out_e, E);

    inv_z<<<(N * 4 + 255) / 256, 256>>>(N);

    edge_aggr<<<(E + 127) / 128, 256>>>(src, dst, out_n, E);
}

// round 13
// speedup vs baseline: 1.4001x; 1.4001x over previous
#include <cuda_runtime.h>
#include <cuda_bf16.h>
#include <cstdint>

// ---------------------------------------------------------------------------
// AggrEGATConv fused EGAT convolution.
//   output: res_n [N,16] followed by res_e [E,16], f32
// ---------------------------------------------------------------------------

#define MAXN 100000
#define MAXE 1600000

__device__ float g_fni [(size_t)MAXN * 64];
__device__ float g_fnj [(size_t)MAXN * 64];
__device__ float g_hsrc[(size_t)MAXN * 64];
__device__ float g_ex  [(size_t)MAXE * 4];
__device__ float g_z   [(size_t)MAXN * 4];
// W_fij bf16 hi/lo, transposed (wt[n][kp]), packed (k,k+1) u32
__device__ unsigned g_wth[64 * 32];
__device__ unsigned g_wtl[64 * 32];
// node weights (W_ni, W_nj, W_src), same transposed bf16 hi/lo form, K=128
__device__ unsigned g_wnh[3 * 64 * 64];
__device__ unsigned g_wnl[3 * 64 * 64];

// ---- helpers ---------------------------------------------------------------
__device__ __forceinline__ void red_add_v4(float* p, float a, float b,
                                           float c, float d) {
    asm volatile("red.global.add.v4.f32 [%0], {%1, %2, %3, %4};"
                 :: "l"(p), "f"(a), "f"(b), "f"(c), "f"(d) : "memory");
}
// split (v0, v1) into packed bf16x2 hi word + packed bf16x2 residual word.
__device__ __forceinline__ void bf16split2(float v0, float v1,
                                           unsigned& h, unsigned& l) {
    asm("cvt.rn.bf16x2.f32 %0, %1, %2;" : "=r"(h) : "f"(v1), "f"(v0));
    float f0 = __uint_as_float(h << 16);
    float f1 = __uint_as_float(h & 0xffff0000u);
    float r0 = v0 - f0;
    float r1 = v1 - f1;
    asm("cvt.rn.bf16x2.f32 %0, %1, %2;" : "=r"(l) : "f"(r1), "f"(r0));
}
__device__ __forceinline__ void mma16816(float& d0, float& d1, float& d2,
                                         float& d3, unsigned a0, unsigned a1,
                                         unsigned a2, unsigned a3,
                                         unsigned b0, unsigned b1) {
    asm volatile(
        "mma.sync.aligned.m16n8k16.row.col.f32.bf16.bf16.f32 "
        "{%0,%1,%2,%3}, {%4,%5,%6,%7}, {%8,%9}, {%0,%1,%2,%3};"
        : "+f"(d0), "+f"(d1), "+f"(d2), "+f"(d3)
        : "r"(a0), "r"(a1), "r"(a2), "r"(a3), "r"(b0), "r"(b1));
}

// edge_main strides (words): 36 mod 32 == 4 -> conflict-free; even -> aligned
#define XS     36
#define WS     36
#define WREG   1152
#define EPS    68
// node_mma strides: 68 mod 32 == 4 -> conflict-free; even -> aligned
#define NXS    68
#define NWREG  2176       // 2 * 16 * NXS

// ---------------------------------------------------------------------------
// Kernel 0: zero res_n and z.
// ---------------------------------------------------------------------------
__global__ void zero_kernel(float* __restrict__ out_n, int N) {
    int i = blockIdx.x * 256 + threadIdx.x;
    if (i < N * 16) out_n[i] = 0.0f;
    if (i < N * 4)  g_z[i]   = 0.0f;
}

// ---------------------------------------------------------------------------
// Kernel W: split all weights into bf16 hi/lo transposed fragment words.
// ---------------------------------------------------------------------------
__global__ void wsplit_all(const float* __restrict__ Wfij,
                           const float* __restrict__ Wni,
                           const float* __restrict__ Wnj,
                           const float* __restrict__ Wsrc) {
    int j = blockIdx.x * 256 + threadIdx.x;
    if (j < 2048) {
        int n  = j >> 5;
        int kp = j & 31;
        float w0 = Wfij[(2 * kp) * 64 + n];
        float w1 = Wfij[(2 * kp + 1) * 64 + n];
        unsigned h, l;
        bf16split2(w0, w1, h, l);
        g_wth[j] = h;
        g_wtl[j] = l;
    } else if (j < 14336) {
        int t = j - 2048;
        int which = t >> 12;          // 0..2
        int r = t & 4095;
        int n  = r >> 6;              // 0..63
        int kp = r & 63;              // 0..63
        const float* W = (which == 0) ? Wni : (which == 1) ? Wnj : Wsrc;
        float w0 = W[(2 * kp) * 64 + n];
        float w1 = W[(2 * kp + 1) * 64 + n];
        unsigned h, l;
        bf16split2(w0, w1, h, l);
        g_wnh[t] = h;
        g_wnl[t] = l;
    }
}

// ---------------------------------------------------------------------------
// Kernel 1: node GEMMs via tensor cores (bf16x3) — R8 version (129us measured).
//   8 warps/block, 128 nodes/block, 16 nodes/warp-tile, K=128 (8 kt).
// ---------------------------------------------------------------------------
__global__ __launch_bounds__(256, 2)
void node_mma(const float* __restrict__ nf,
              const float* __restrict__ bsrc,
              int N)
{
    extern __shared__ char dyns[];
    unsigned* s_wh = (unsigned*)dyns;                    // 64*NXS
    unsigned* s_wl = s_wh + 64 * NXS;                    // 64*NXS
    unsigned* s_x  = s_wl + 64 * NXS;                    // 8*NWREG
    float*    sb   = (float*)(s_x + 8 * NWREG);          // 64

    const int tid  = threadIdx.x;
    const int lane = tid & 31;
    const int w    = tid >> 5;
    const int which = blockIdx.y;

    const unsigned* wnh = g_wnh + which * 4096;
    const unsigned* wnl = g_wnl + which * 4096;
    for (int j = tid; j < 4096; j += 256) {
        int n = j >> 6, kp = j & 63;
        s_wh[n * NXS + kp] = wnh[j];
        s_wl[n * NXS + kp] = wnl[j];
    }
    if (tid < 64) sb[tid] = (which == 2) ? bsrc[tid] : 0.0f;

    const int nbase = blockIdx.x * 128;
    {
        const float4* nf4 = (const float4*)nf;
#pragma unroll
        for (int i = 0; i < 16; ++i) {
            int idx = i * 256 + tid;             // 0..4095
            int r  = idx >> 5;                   // local row 0..127
            int ch = idx & 31;                   // float4 chunk 0..31
            float4 v = make_float4(0.f, 0.f, 0.f, 0.f);
            if (nbase + r < N) v = nf4[(size_t)(nbase + r) * 32 + ch];
            unsigned h0, l0, h1, l1;
            bf16split2(v.x, v.y, h0, l0);
            bf16split2(v.z, v.w, h1, l1);
            unsigned* base = s_x + (r >> 4) * NWREG + (r & 15) * NXS + ch * 2;
            *(uint2*)(base)            = make_uint2(h0, h1);
            *(uint2*)(base + 16 * NXS) = make_uint2(l0, l1);
        }
    }
    __syncthreads();

    const int g = lane >> 2;
    const int q = lane & 3;

    float acc[8][4];
#pragma unroll
    for (int nt = 0; nt < 8; ++nt)
#pragma unroll
        for (int i = 0; i < 4; ++i) acc[nt][i] = 0.0f;

    const unsigned* xh0 = s_x + w * NWREG + g * NXS;
    const unsigned* xh8 = xh0 + 8 * NXS;
    const unsigned* xl0 = xh0 + 16 * NXS;
    const unsigned* xl8 = xl0 + 8 * NXS;

#pragma unroll
    for (int kt = 0; kt < 8; ++kt) {
        const int kp = kt * 8 + q;
        unsigned ah0 = xh0[kp],     ah1 = xh8[kp];
        unsigned ah2 = xh0[kp + 4], ah3 = xh8[kp + 4];
        unsigned al0 = xl0[kp],     al1 = xl8[kp];
        unsigned al2 = xl0[kp + 4], al3 = xl8[kp + 4];
#pragma unroll
        for (int nt = 0; nt < 8; ++nt) {
            const unsigned* wb  = s_wh + (nt * 8 + g) * NXS + kp;
            const unsigned* wlb = s_wl + (nt * 8 + g) * NXS + kp;
            unsigned bh0 = wb[0],  bh1 = wb[4];
            unsigned bl0 = wlb[0], bl1 = wlb[4];
            mma16816(acc[nt][0], acc[nt][1], acc[nt][2], acc[nt][3],
                     ah0, ah1, ah2, ah3, bh0, bh1);
            mma16816(acc[nt][0], acc[nt][1], acc[nt][2], acc[nt][3],
                     ah0, ah1, ah2, ah3, bl0, bl1);
            mma16816(acc[nt][0], acc[nt][1], acc[nt][2], acc[nt][3],
                     al0, al1, al2, al3, bh0, bh1);
        }
    }
    __syncwarp();

    float* epiw = (float*)(s_x + w * NWREG);
#pragma unroll
    for (int nt = 0; nt < 8; ++nt) {
        const int c = nt * 8 + 2 * q;
        *(float2*)(epiw + g * 66 + c)       = make_float2(acc[nt][0], acc[nt][1]);
        *(float2*)(epiw + (g + 8) * 66 + c) = make_float2(acc[nt][2], acc[nt][3]);
    }
    __syncwarp();

    float* out = (which == 0) ? g_fni : (which == 1) ? g_fnj : g_hsrc;
    const float bb0 = sb[2 * lane];
    const float bb1 = sb[2 * lane + 1];
    const int rowbase = nbase + w * 16;
#pragma unroll 4
    for (int r = 0; r < 16; ++r) {
        if (rowbase + r >= N) break;
        float2 v = *(const float2*)(epiw + r * 66 + 2 * lane);
        *(float2*)(out + (size_t)(rowbase + r) * 64 + 2 * lane) =
            make_float2(v.x + bb0, v.y + bb1);
    }
}

// ---------------------------------------------------------------------------
// Kernel 2: edge pass 1 via tensor cores (bf16x3, R11 version, 300us).
// ---------------------------------------------------------------------------
__global__ __launch_bounds__(256, 4)
void edge_main(const float* __restrict__ efeats,
               const int*   __restrict__ src,
               const int*   __restrict__ dst,
               const float* __restrict__ attn,
               const float* __restrict__ bias_e,
               float* __restrict__ out_e,
               int E)
{
    extern __shared__ char dyns[];
    unsigned* s_wh = (unsigned*)dyns;
    unsigned* s_wl = s_wh + 64 * WS;
    unsigned* s_x  = s_wl + 64 * WS;
    float*    s_attn = (float*)(s_x + 8 * WREG);
    float*    s_bias = s_attn + 64;

    const int tid  = threadIdx.x;
    const int lane = tid & 31;
    const int w    = tid >> 5;

    for (int j = tid; j < 2048; j += 256) {
        int n = j >> 5, kp = j & 31;
        s_wh[n * WS + kp] = g_wth[j];
        s_wl[n * WS + kp] = g_wtl[j];
    }
    if (tid < 64) {
        s_attn[tid] = attn[tid];
        s_bias[tid] = bias_e[tid];
    }

    const long long eblk = (long long)blockIdx.x * 128;
    {
        const float4* ef4 = (const float4*)efeats;
#pragma unroll
        for (int i = 0; i < 8; ++i) {
            int idx = i * 256 + tid;
            int e  = idx >> 4;
            int ch = idx & 15;
            float4 v = make_float4(0.f, 0.f, 0.f, 0.f);
            if (eblk + e < E) v = ef4[(eblk + e) * 16 + ch];
            unsigned h0, l0, h1, l1;
            bf16split2(v.x, v.y, h0, l0);
            bf16split2(v.z, v.w, h1, l1);
            unsigned* base = s_x + (e >> 4) * WREG + (e & 15) * XS + ch * 2;
            *(uint2*)(base)            = make_uint2(h0, h1);
            *(uint2*)(base + 16 * XS)  = make_uint2(l0, l1);
        }
    }
    __syncthreads();

    const long long ewarp = eblk + w * 16;
    const int g = lane >> 2;
    const int q = lane & 3;

    int myS = 0, myD = 0;
    if (lane < 16 && ewarp + lane < E) {
        myS = src[ewarp + lane];
        myD = dst[ewarp + lane];
    }

    float acc[8][4];
#pragma unroll
    for (int nt = 0; nt < 8; ++nt)
#pragma unroll
        for (int i = 0; i < 4; ++i) acc[nt][i] = 0.0f;

    const unsigned* xh0 = s_x + w * WREG + g * XS;
    const unsigned* xh8 = xh0 + 8 * XS;
    const unsigned* xl0 = xh0 + 16 * XS;
    const unsigned* xl8 = xl0 + 8 * XS;

#pragma unroll
    for (int kt = 0; kt < 4; ++kt) {
        const int kp = kt * 8 + q;
        unsigned ah0 = xh0[kp],     ah1 = xh8[kp];
        unsigned ah2 = xh0[kp + 4], ah3 = xh8[kp + 4];
        unsigned al0 = xl0[kp],     al1 = xl8[kp];
        unsigned al2 = xl0[kp + 4], al3 = xl8[kp + 4];
#pragma unroll
        for (int nt = 0; nt < 8; ++nt) {
            const unsigned* wb  = s_wh + (nt * 8 + g) * WS + kp;
            const unsigned* wlb = s_wl + (nt * 8 + g) * WS + kp;
            unsigned bh0 = wb[0],  bh1 = wb[4];
            unsigned bl0 = wlb[0], bl1 = wlb[4];
            mma16816(acc[nt][0], acc[nt][1], acc[nt][2], acc[nt][3],
                     ah0, ah1, ah2, ah3, bh0, bh1);
            mma16816(acc[nt][0], acc[nt][1], acc[nt][2], acc[nt][3],
                     ah0, ah1, ah2, ah3, bl0, bl1);
            mma16816(acc[nt][0], acc[nt][1], acc[nt][2], acc[nt][3],
                     al0, al1, al2, al3, bh0, bh1);
        }
    }
    __syncwarp();

    float* epiw = (float*)(s_x + w * WREG);
#pragma unroll
    for (int nt = 0; nt < 8; ++nt) {
        const int c = nt * 8 + 2 * q;
        *(float2*)(epiw + g * EPS + c)       = make_float2(acc[nt][0], acc[nt][1]);
        *(float2*)(epiw + (g + 8) * EPS + c) = make_float2(acc[nt][2], acc[nt][3]);
    }
    __syncwarp();

    const int half = lane >> 4;
    const int hl   = lane & 15;
    const float4 bias4 = *(const float4*)(s_bias + 4 * hl);
    const float4 attn4 = *(const float4*)(s_attn + 4 * hl);

#pragma unroll 2
    for (int r2 = 0; r2 < 8; ++r2) {
        const int row = 2 * r2 + half;
        const long long e_r = ewarp + row;
        if (ewarp + 2 * r2 >= E) break;
        const bool valid = (e_r < E);
        const int s_r = __shfl_sync(0xffffffffu, myS, row);
        const int d_r = __shfl_sync(0xffffffffu, myD, row);

        float4 fa = *(const float4*)(g_fni + (size_t)s_r * 64 + 4 * hl);
        float4 fb = *(const float4*)(g_fnj + (size_t)d_r * 64 + 4 * hl);
        float4 ac = *(const float4*)(epiw + row * EPS + 4 * hl);

        float y0 = ac.x + fa.x + fb.x + bias4.x;
        float y1 = ac.y + fa.y + fb.y + bias4.y;
        float y2 = ac.z + fa.z + fb.z + bias4.z;
        float y3 = ac.w + fa.w + fb.w + bias4.w;
        y0 = (y0 > 0.0f) ? y0 : 0.01f * y0;
        y1 = (y1 > 0.0f) ? y1 : 0.01f * y1;
        y2 = (y2 > 0.0f) ? y2 : 0.01f * y2;
        y3 = (y3 > 0.0f) ? y3 : 0.01f * y3;

        float lp = y0 * attn4.x + y1 * attn4.y + y2 * attn4.z + y3 * attn4.w;
        lp += __shfl_xor_sync(0xffffffffu, lp, 1);
        lp += __shfl_xor_sync(0xffffffffu, lp, 2);

        y0 += __shfl_xor_sync(0xffffffffu, y0, 4);
        y0 += __shfl_xor_sync(0xffffffffu, y0, 8);
        y1 += __shfl_xor_sync(0xffffffffu, y1, 4);
        y1 += __shfl_xor_sync(0xffffffffu, y1, 8);
        y2 += __shfl_xor_sync(0xffffffffu, y2, 4);
        y2 += __shfl_xor_sync(0xffffffffu, y2, 8);
        y3 += __shfl_xor_sync(0xffffffffu, y3, 4);
        y3 += __shfl_xor_sync(0xffffffffu, y3, 8);

        if (valid && hl < 4)
            *(float4*)(out_e + (size_t)e_r * 16 + 4 * hl) =
                make_float4(0.25f * y0, 0.25f * y1, 0.25f * y2, 0.25f * y3);

        const int hb = lane & 16;
        float l0 = __shfl_sync(0xffffffffu, lp, hb + 0);
        float l1 = __shfl_sync(0xffffffffu, lp, hb + 4);
        float l2 = __shfl_sync(0xffffffffu, lp, hb + 8);
        float l3 = __shfl_sync(0xffffffffu, lp, hb + 12);
        if (valid && hl == 0) {
            float e0 = expf(l0), e1 = expf(l1), e2 = expf(l2), e3 = expf(l3);
            *(float4*)(g_ex + (size_t)e_r * 4) = make_float4(e0, e1, e2, e3);
            red_add_v4(&g_z[(size_t)d_r * 4], e0, e1, e2, e3);
        }
    }
}

// ---------------------------------------------------------------------------
// Kernel 3: invert z once per (node, head)
// ---------------------------------------------------------------------------
__global__ void inv_z(int N) {
    int i = blockIdx.x * 256 + threadIdx.x;
    if (i < N * 4) g_z[i] = __frcp_rn(g_z[i]);
}

// ---------------------------------------------------------------------------
// Kernel 4: edge pass 2 (R12 version, 55us measured).
// ---------------------------------------------------------------------------
__global__ __launch_bounds__(256)
void edge_aggr(const int* __restrict__ src,
               const int* __restrict__ dst,
               float* __restrict__ out_n,
               int E)
{
    const int tid  = threadIdx.x;
    const int lane = tid & 31;
    const int t    = lane & 3;
    const long long ebase = (long long)blockIdx.x * 128 + (tid >> 5) * 16
                            + (lane >> 2);
    const long long e0 = ebase;
    const long long e1 = ebase + 8;
    const bool v0ok = (e0 < E);
    const bool v1ok = (e1 < E);
    if (!v0ok) return;

    const int s0 = src[e0];
    const int d0 = dst[e0];
    const int s1 = v1ok ? src[e1] : 0;
    const int d1 = v1ok ? dst[e1] : 0;

    float4 exA = *(const float4*)(g_ex + (size_t)e0 * 4);
    float4 ziA = *(const float4*)(g_z  + (size_t)d0 * 4);
    float4 exB = make_float4(0.f, 0.f, 0.f, 0.f);
    float4 ziB = make_float4(0.f, 0.f, 0.f, 0.f);
    if (v1ok) {
        exB = *(const float4*)(g_ex + (size_t)e1 * 4);
        ziB = *(const float4*)(g_z  + (size_t)d1 * 4);
    }

    const float* hrA = g_hsrc + (size_t)s0 * 64 + 4 * t;
    const float* hrB = g_hsrc + (size_t)s1 * 64 + 4 * t;
    float4 a0v = *(const float4*)(hrA);
    float4 a1v = *(const float4*)(hrA + 16);
    float4 a2v = *(const float4*)(hrA + 32);
    float4 a3v = *(const float4*)(hrA + 48);
    float4 b0v, b1v, b2v, b3v;
    if (v1ok) {
        b0v = *(const float4*)(hrB);
        b1v = *(const float4*)(hrB + 16);
        b2v = *(const float4*)(hrB + 32);
        b3v = *(const float4*)(hrB + 48);
    }

    {
        const float a0 = 0.25f * exA.x * ziA.x;
        const float a1 = 0.25f * exA.y * ziA.y;
        const float a2 = 0.25f * exA.z * ziA.z;
        const float a3 = 0.25f * exA.w * ziA.w;
        float m0 = a0 * a0v.x + a1 * a1v.x + a2 * a2v.x + a3 * a3v.x;
        float m1 = a0 * a0v.y + a1 * a1v.y + a2 * a2v.y + a3 * a3v.y;
        float m2 = a0 * a0v.z + a1 * a1v.z + a2 * a2v.z + a3 * a3v.z;
        float m3 = a0 * a0v.w + a1 * a1v.w + a2 * a2v.w + a3 * a3v.w;
        red_add_v4(out_n + (size_t)d0 * 16 + 4 * t, m0, m1, m2, m3);
    }
    if (v1ok) {
        const float a0 = 0.25f * exB.x * ziB.x;
        const float a1 = 0.25f * exB.y * ziB.y;
        const float a2 = 0.25f * exB.z * ziB.z;
        const float a3 = 0.25f * exB.w * ziB.w;
        float m0 = a0 * b0v.x + a1 * b1v.x + a2 * b2v.x + a3 * b3v.x;
        float m1 = a0 * b0v.y + a1 * b1v.y + a2 * b2v.y + a3 * b3v.y;
        float m2 = a0 * b0v.z + a1 * b1v.z + a2 * b2v.z + a3 * b3v.z;
        float m3 = a0 * b0v.w + a1 * b1v.w + a2 * b2v.w + a3 * b3v.w;
        red_add_v4(out_n + (size_t)d1 * 16 + 4 * t, m0, m1, m2, m3);
    }
}

// ---------------------------------------------------------------------------
extern "C" void kernel_launch(void* const* d_in, const int* in_sizes, int n_in,
                              void* d_out, int out_size)
{
    const float* nfeats = (const float*)d_in[0];
    const float* efeats = (const float*)d_in[1];
    const int*   src    = (const int*)  d_in[2];
    const int*   dst    = (const int*)  d_in[3];
    const float* Wni    = (const float*)d_in[4];
    const float* Wnj    = (const float*)d_in[5];
    const float* Wfij   = (const float*)d_in[6];
    const float* Wsrc   = (const float*)d_in[7];
    const float* bsrc   = (const float*)d_in[8];
    const float* attn   = (const float*)d_in[9];
    const float* biase  = (const float*)d_in[10];

    const int N = in_sizes[0] / 128;
    const int E = in_sizes[2];

    float* out_n = (float*)d_out;
    float* out_e = out_n + (size_t)N * 16;

    static int smem_set = 0;
    const int EM_SMEM = (64 * WS * 2 + 8 * WREG + 128) * 4;        // 55808 B
    const int NM_SMEM = (64 * NXS * 2 + 8 * NWREG + 64) * 4;       // 104704 B
    if (!smem_set) {
        cudaFuncSetAttribute(edge_main,
                             cudaFuncAttributeMaxDynamicSharedMemorySize,
                             EM_SMEM);
        cudaFuncSetAttribute(node_mma,
                             cudaFuncAttributeMaxDynamicSharedMemorySize,
                             NM_SMEM);
        smem_set = 1;
    }

    // launch order: idx 3 (ncu's pick) = edge_main
    zero_kernel<<<(N * 16 + 255) / 256, 256>>>(out_n, N);

    wsplit_all<<<56, 256>>>(Wfij, Wni, Wnj, Wsrc);

    dim3 gn((N + 127) / 128, 3);
    node_mma<<<gn, 256, NM_SMEM>>>(nfeats, bsrc, N);

    edge_main<<<(E + 127) / 128, 256, EM_SMEM>>>(efeats, src, dst,
                                                 attn, biase, out_e, E);

    inv_z<<<(N * 4 + 255) / 256, 256>>>(N);

    edge_aggr<<<(E + 127) / 128, 256>>>(src, dst, out_n, E);
}